// round 1
// baseline (speedup 1.0000x reference)
#include <cuda_runtime.h>
#include <cstdint>

// Problem constants
#define B_      32
#define CIN     64
#define COUT    64
#define HH      56
#define WW      56
#define LL      3136          // 56*56
#define FEAT    576           // 64*3*3

#define NTHREADS      128
#define CHUNK_F       64      // f-columns per weight chunk
#define NCHUNK        9       // 576/64
#define FQ_PER_CHUNK  16      // float4's per chunk row
#define PATCH_F4      144     // 576/4

// smem: patch [32][576] fp32 = 73728 B, then w4 [2][16][64] float4 = 32768 B
#define SMEM_PATCH_BYTES (B_ * FEAT * 4)
#define SMEM_W_OFF       SMEM_PATCH_BYTES
#define SMEM_TOTAL       (SMEM_PATCH_BYTES + 2 * FQ_PER_CHUNK * COUT * 16)

using ull = unsigned long long;

// Packed dual-fp32 FMA: acc.{lo,hi} += a.{lo,hi} * b.{lo,hi}
// mov.b64 packs of adjacent LDS.128 dest registers alias to register pairs
// (ptxas pair-allocates), so this should compile to a single FFMA2 in SASS.
__device__ __forceinline__ void fma2(ull& acc, float ax, float ay, float bx, float by) {
    asm("{\n\t"
        ".reg .b64 a, b;\n\t"
        "mov.b64 a, {%1, %2};\n\t"
        "mov.b64 b, {%3, %4};\n\t"
        "fma.rn.f32x2 %0, a, b, %0;\n\t"
        "}"
        : "+l"(acc)
        : "f"(ax), "f"(ay), "f"(bx), "f"(by));
}

__device__ __forceinline__ void unpack2(ull v, float& lo, float& hi) {
    asm("mov.b64 {%0, %1}, %2;" : "=f"(lo), "=f"(hi) : "l"(v));
}

__device__ __forceinline__ void cp_async16(void* smem_ptr, const void* gmem_ptr) {
    uint32_t s = (uint32_t)__cvta_generic_to_shared(smem_ptr);
    asm volatile("cp.async.cg.shared.global [%0], [%1], 16;\n" :: "r"(s), "l"(gmem_ptr));
}

__global__ void __launch_bounds__(NTHREADS, 2)
lc2d_kernel(const float* __restrict__ x,
            const float* __restrict__ w,
            const float* __restrict__ bias,
            float* __restrict__ out)
{
    extern __shared__ char smem[];
    float*  ps = (float*)smem;                      // patch  [32][576]
    float4* p4 = (float4*)smem;                     // patch  [32][144] as float4
    float4* w4 = (float4*)(smem + SMEM_W_OFF);      // weight [2][16][64] float4

    const int tid  = threadIdx.x;
    const int lane = tid & 31;
    const int warp = tid >> 5;
    const int l    = blockIdx.x;
    const int oh   = l / WW;
    const int ow   = l - oh * WW;

    const float* wl = w + (size_t)l * (COUT * FEAT);

    // ---- issue weight chunk 0 (cp.async, buf 0) ----
    {
        #pragma unroll
        for (int j = 0; j < 8; j++) {
            int idx = tid + NTHREADS * j;       // 0..1023
            int fq  = idx & 15;
            int c   = idx >> 4;
            cp_async16(&w4[0 * 1024 + fq * 64 + c], wl + c * FEAT + 4 * fq);
        }
        asm volatile("cp.async.commit_group;\n");
    }

    // ---- stage patch tile (overlaps chunk-0 arrival) ----
    for (int idx = tid; idx < B_ * FEAT; idx += NTHREADS) {
        int b   = idx / FEAT;
        int f   = idx - b * FEAT;
        int cin = f / 9;
        int r   = f - cin * 9;
        int ki  = r / 3;
        int kj  = r - ki * 3;
        int h   = oh + ki - 1;
        int wc  = ow + kj - 1;
        float v = 0.0f;
        if ((unsigned)h < HH && (unsigned)wc < WW)
            v = x[(((size_t)b * CIN + cin) * HH + h) * WW + wc];
        ps[idx] = v;
    }

    // accumulators: even/odd-f partial sums packed as f32x2
    ull accA[8], accB[8];
    #pragma unroll
    for (int i = 0; i < 8; i++) { accA[i] = 0ull; accB[i] = 0ull; }

    const int b0 = warp * 8;

    for (int k = 0; k < NCHUNK; k++) {
        // issue chunk k+1 into buffer (k+1)&1 (that buffer was consumed in iter k-1)
        if (k + 1 < NCHUNK) {
            const int f0  = (k + 1) * CHUNK_F;
            const int buf = (k + 1) & 1;
            #pragma unroll
            for (int j = 0; j < 8; j++) {
                int idx = tid + NTHREADS * j;
                int fq  = idx & 15;
                int c   = idx >> 4;
                cp_async16(&w4[buf * 1024 + fq * 64 + c], wl + c * FEAT + f0 + 4 * fq);
            }
            asm volatile("cp.async.commit_group;\n");
            asm volatile("cp.async.wait_group 1;\n");
        } else {
            asm volatile("cp.async.wait_group 0;\n");
        }
        __syncthreads();

        const float4* wbuf = &w4[(k & 1) * 1024];
        const int fqa0 = k * FQ_PER_CHUNK;

        #pragma unroll
        for (int fq = 0; fq < FQ_PER_CHUNK; fq++) {
            float4 wa = wbuf[fq * 64 + lane];        // c = lane        (conflict-free)
            float4 wb = wbuf[fq * 64 + lane + 32];   // c = lane + 32   (conflict-free)
            #pragma unroll
            for (int i = 0; i < 8; i++) {
                float4 p = p4[(b0 + i) * PATCH_F4 + fqa0 + fq];   // broadcast
                fma2(accA[i], p.x, p.y, wa.x, wa.y);
                fma2(accA[i], p.z, p.w, wa.z, wa.w);
                fma2(accB[i], p.x, p.y, wb.x, wb.y);
                fma2(accB[i], p.z, p.w, wb.z, wb.w);
            }
        }
        __syncthreads();
    }

    // ---- epilogue ----
    const float* bl = bias + (size_t)l * COUT;
    const float bc0 = bl[lane];
    const float bc1 = bl[lane + 32];

    #pragma unroll
    for (int i = 0; i < 8; i++) {
        float lo, hi;
        unpack2(accA[i], lo, hi);
        float sA = lo + hi + bc0;
        unpack2(accB[i], lo, hi);
        float sB = lo + hi + bc1;
        int b = b0 + i;
        out[((size_t)(b * COUT) + lane)      * LL + l] = sA;
        out[((size_t)(b * COUT) + lane + 32) * LL + l] = sB;
    }
}

extern "C" void kernel_launch(void* const* d_in, const int* in_sizes, int n_in,
                              void* d_out, int out_size)
{
    const float* x    = (const float*)d_in[0];   // [32,64,56,56]
    const float* w    = (const float*)d_in[1];   // [3136,64,576]
    const float* bias = (const float*)d_in[2];   // [3136,64]
    float* out        = (float*)d_out;           // [32,64,56,56]

    cudaFuncSetAttribute(lc2d_kernel, cudaFuncAttributeMaxDynamicSharedMemorySize, SMEM_TOTAL);
    lc2d_kernel<<<LL, NTHREADS, SMEM_TOTAL>>>(x, w, bias, out);
}

// round 2
// speedup vs baseline: 1.1216x; 1.1216x over previous
#include <cuda_runtime.h>
#include <cstdint>

// Problem constants
#define B_      32
#define CIN     64
#define COUT    64
#define HH      56
#define WW      56
#define LL      3136          // 56*56
#define FEAT    576           // 64*3*3

#define NTHREADS      128
#define CHUNK_F       64      // f-columns per weight chunk
#define NCHUNK        9       // 576/64
#define FQ_PER_CHUNK  16      // float4's per chunk row

// patch smem: [32][145] float4 (row padded to odd f4 count -> conflict-free
// for loads of 4 consecutive b rows).  145*16 = 2320 B/row.
#define PROW_F4       145
#define PROW_FLOATS   (PROW_F4 * 4)          // 580
#define SMEM_PATCH_BYTES (B_ * PROW_F4 * 16) // 74240
#define SMEM_W_OFF       SMEM_PATCH_BYTES
// weight: [2 buf][16 fq][64 c] float4 = 32768 B
#define SMEM_TOTAL       (SMEM_PATCH_BYTES + 2 * FQ_PER_CHUNK * COUT * 16)

using ull = unsigned long long;

struct U2 { ull lo, hi; };

// one LDS.128 -> two packed f32x2 operands, no movs
__device__ __forceinline__ U2 lds128(uint32_t addr) {
    U2 r;
    asm volatile("ld.shared.v2.u64 {%0, %1}, [%2];"
                 : "=l"(r.lo), "=l"(r.hi) : "r"(addr));
    return r;
}

// acc.{lo,hi} += a.{lo,hi} * b.{lo,hi}  (single FFMA2)
__device__ __forceinline__ void fma2(ull& acc, ull a, ull b) {
    asm("fma.rn.f32x2 %0, %1, %2, %0;" : "+l"(acc) : "l"(a), "l"(b));
}

__device__ __forceinline__ float hsum2(ull v) {
    float lo, hi;
    asm("mov.b64 {%0, %1}, %2;" : "=f"(lo), "=f"(hi) : "l"(v));
    return lo + hi;
}

__device__ __forceinline__ void cp_async16(uint32_t smem_addr, const void* gmem_ptr) {
    asm volatile("cp.async.cg.shared.global [%0], [%1], 16;\n"
                 :: "r"(smem_addr), "l"(gmem_ptr));
}

__global__ void __launch_bounds__(NTHREADS, 2)
lc2d_kernel(const float* __restrict__ x,
            const float* __restrict__ w,
            const float* __restrict__ bias,
            float* __restrict__ out)
{
    extern __shared__ char smem[];
    float* ps = (float*)smem;                         // patch [32][580] floats
    const uint32_t sbase = (uint32_t)__cvta_generic_to_shared(smem);
    const uint32_t wsmem = sbase + SMEM_W_OFF;        // weight f4 area

    const int tid  = threadIdx.x;
    const int lane = tid & 31;
    const int warp = tid >> 5;
    const int l    = blockIdx.x;
    const int oh   = l / WW;
    const int ow   = l - oh * WW;

    const float* wl = w + (size_t)l * (COUT * FEAT);

    // weight cp.async mapping (same for every chunk): thread j-th element
    const int wfq = tid & 15;        // fq within chunk
    const int wch = tid >> 4;        // base channel (step 8 per j)
    const float* wg0 = wl + (size_t)wch * FEAT + 4 * wfq;
    const uint32_t wsd0 = wsmem + (uint32_t)(wfq * 64 + wch) * 16;

    // ---- issue weight chunk 0 (buf 0) ----
    {
        #pragma unroll
        for (int j = 0; j < 8; j++)
            cp_async16(wsd0 + j * 8 * 16, wg0 + (size_t)j * 8 * FEAT);
        asm volatile("cp.async.commit_group;\n");
    }

    // ---- stage patch tile, f-outer (few div/mods), overlaps chunk-0 ----
    for (int f = tid; f < FEAT; f += NTHREADS) {
        int cin = f / 9;
        int r   = f - cin * 9;
        int ki  = r / 3;
        int kj  = r - ki * 3;
        int h   = oh + ki - 1;
        int wc  = ow + kj - 1;
        bool ok = ((unsigned)h < HH) & ((unsigned)wc < WW);
        const float* xp = x + ((size_t)cin * HH + h) * WW + wc;
        float* pp = ps + f;
        #pragma unroll 8
        for (int b = 0; b < B_; b++) {
            float v = ok ? xp[(size_t)b * (CIN * HH * WW)] : 0.0f;
            pp[b * PROW_FLOATS] = v;
        }
    }

    // thread tile: 4 batches x 4 channels
    // warp grid 2x2: wbq = warp>>1 (batch half), wcq = warp&1 (channel half)
    const int b0 = (warp >> 1) * 16 + (lane >> 3);   // + 4*i, i<4
    const int c0 = (warp & 1) * 32 + (lane & 7);     // + 8*j, j<4

    // smem byte addresses
    const uint32_t paddr0 = sbase + (uint32_t)(b0 * PROW_F4) * 16;  // + (k*16+fq)*16, + i*4 rows
    const uint32_t waddrC = (uint32_t)c0 * 16;                       // + fq*64*16 + j*8*16 (+buf)

    ull acc[16];
    #pragma unroll
    for (int i = 0; i < 16; i++) acc[i] = 0ull;

    for (int k = 0; k < NCHUNK; k++) {
        if (k + 1 < NCHUNK) {
            const int f0  = (k + 1) * CHUNK_F;
            const uint32_t bufoff = (uint32_t)(((k + 1) & 1) * 1024 * 16);
            #pragma unroll
            for (int j = 0; j < 8; j++)
                cp_async16(wsd0 + bufoff + j * 8 * 16, wg0 + f0 + (size_t)j * 8 * FEAT);
            asm volatile("cp.async.commit_group;\n");
            asm volatile("cp.async.wait_group 1;\n");
        } else {
            asm volatile("cp.async.wait_group 0;\n");
        }
        __syncthreads();

        const uint32_t wb_addr = wsmem + (uint32_t)((k & 1) * 1024 * 16) + waddrC;
        const uint32_t p_addr  = paddr0 + (uint32_t)(k * FQ_PER_CHUNK) * 16;

        #pragma unroll
        for (int fq = 0; fq < FQ_PER_CHUNK; fq++) {
            U2 wv[4], pv[4];
            #pragma unroll
            for (int j = 0; j < 4; j++)
                wv[j] = lds128(wb_addr + (uint32_t)fq * 1024 + j * 128);
            #pragma unroll
            for (int i = 0; i < 4; i++)
                pv[i] = lds128(p_addr + (uint32_t)fq * 16 + i * 4 * PROW_F4 * 16);
            #pragma unroll
            for (int i = 0; i < 4; i++) {
                #pragma unroll
                for (int j = 0; j < 4; j++) {
                    fma2(acc[i * 4 + j], pv[i].lo, wv[j].lo);
                    fma2(acc[i * 4 + j], pv[i].hi, wv[j].hi);
                }
            }
        }
        __syncthreads();
    }

    // ---- epilogue ----
    const float* bl = bias + (size_t)l * COUT;
    #pragma unroll
    for (int j = 0; j < 4; j++) {
        const int c = c0 + 8 * j;
        const float bc = bl[c];
        #pragma unroll
        for (int i = 0; i < 4; i++) {
            const int b = b0 + 4 * i;
            out[((size_t)(b * COUT) + c) * LL + l] = hsum2(acc[i * 4 + j]) + bc;
        }
    }
}

extern "C" void kernel_launch(void* const* d_in, const int* in_sizes, int n_in,
                              void* d_out, int out_size)
{
    const float* x    = (const float*)d_in[0];   // [32,64,56,56]
    const float* w    = (const float*)d_in[1];   // [3136,64,576]
    const float* bias = (const float*)d_in[2];   // [3136,64]
    float* out        = (float*)d_out;           // [32,64,56,56]

    cudaFuncSetAttribute(lc2d_kernel, cudaFuncAttributeMaxDynamicSharedMemorySize, SMEM_TOTAL);
    lc2d_kernel<<<LL, NTHREADS, SMEM_TOTAL>>>(x, w, bias, out);
}